// round 16
// baseline (speedup 1.0000x reference)
#include <cuda_runtime.h>

#define F 8
#define T 512
#define NN 512
#define NR 128
#define FT 4096
#define NW 1024
#define BS 32
#define NB 16
#define NITER 12
#define GBS 64
#define SMS 68

__device__ float g_K0[F * T * T];
__device__ float g_Kw[F * T * T];
__device__ float g_Wn[F * T * T];
__device__ float g_Sf[T * T];
__device__ float g_crinv[F * NN], g_crc[F * F], g_cd[F], g_invd[FT];
__device__ float g_B[FT * NR], g_X[FT * NR], g_Rv[FT * NR];
__device__ float g_Z[FT * NR], g_P[FT * NR], g_AP[FT * NR];
__device__ float g_pAp[128 * NR];
__device__ float g_zp0[64 * NR];
__device__ float4 g_zpp[256 * 32];
__device__ float g_rho[2][NR], g_al[NR], g_be[NR];

// ---------- setup (proven verbatim) ----------
__global__ void k_setup(const float* __restrict__ Cm, const float* __restrict__ dm,
                        const float* __restrict__ rd) {
    int tid = threadIdx.x;
    for (int i = tid; i < F * NN; i += 256) {
        int f = i / NN, n = i % NN;
        g_crinv[f * NN + n] = Cm[n * F + f] / rd[n];
    }
    __syncthreads();
    int w = tid >> 5, l = tid & 31;
    for (int q = 0; q < 8; q++) {
        int e = w * 8 + q, i = e / F, j = e % F;
        float s = 0.f;
        for (int n = l; n < NN; n += 32) s += g_crinv[i * NN + n] * Cm[n * F + j];
        for (int o = 16; o; o >>= 1) s += __shfl_xor_sync(0xffffffffu, s, o);
        if (l == 0) g_crc[e] = s;
    }
    {
        float s = 0.f;
        for (int n = l; n < NN; n += 32) s += g_crinv[w * NN + n] * dm[n];
        for (int o = 16; o; o >>= 1) s += __shfl_xor_sync(0xffffffffu, s, o);
        if (l == 0) g_cd[w] = s;
    }
}

// ---------- build K (proven verbatim) ----------
__global__ void k_buildK(const float* __restrict__ gm) {
    int t = blockIdx.x, f = blockIdx.y;
    float g = gm[f];
    size_t base = ((size_t)f * T + t) * T;
    for (int u = threadIdx.x; u < T; u += blockDim.x) {
        float d = (float)(t - u);
        float v = (1.0f - 1e-3f) * expf(-0.5f * g * d * d);
        if (u == t) v += 1e-3f;
        g_K0[base + u] = v;
        g_Kw[base + u] = v;
    }
}

// ---------- in-smem 32x32 GJ pivot inversion (verbatim k_diag body) ----------
__device__ __forceinline__ void gj32(float* s, int tid) {
    for (int p = 0; p < BS; p++) {
        float pv = 1.0f / s[p * 33 + p];
        for (int j = tid; j < BS; j += 256) if (j != p) s[p * 33 + j] *= pv;
        __syncthreads();
        for (int i = tid; i < BS * BS; i += 256) {
            int r = i >> 5, c = i & 31;
            if (r != p && c != p) s[r * 33 + c] -= s[r * 33 + p] * s[p * 33 + c];
        }
        __syncthreads();
        for (int i = tid; i < BS; i += 256) if (i != p) s[i * 33 + p] *= -pv;
        if (tid == 0) s[p * 33 + p] = pv;
        __syncthreads();
    }
}

__device__ __forceinline__ void mm32f(const float* sA, const float* sB,
                                      float acc[2][2], int ty, int tx) {
    for (int kk = 0; kk < BS; kk++) {
        float a0 = sA[(ty + 0) * 33 + kk], a1 = sA[(ty + 1) * 33 + kk];
        float b0 = sB[kk * 33 + tx + 0], b1 = sB[kk * 33 + tx + 1];
        acc[0][0] += a0 * b0; acc[0][1] += a0 * b1;
        acc[1][0] += a1 * b0; acc[1][1] += a1 * b1;
    }
}

// ---------- sweep step kernel 1: interior update (reads only OLD k-row/col/diag) --
// A[ib][jb] -= A[ib][k]_old * (Di * A[k][jb]_old),  ib,jb != k
__global__ void __launch_bounds__(256) k_sw_int(int k) {
    int f = blockIdx.x;
    int ib = blockIdx.y + (blockIdx.y >= k ? 1 : 0);
    int jb = blockIdx.z + (blockIdx.z >= k ? 1 : 0);
    __shared__ float sD[BS * 33], sAkj[BS * 33], sBB[BS * 33], sAik[BS * 33];
    float* A = g_Kw + (size_t)f * T * T;
    int tid = threadIdx.x;
    for (int i = tid; i < BS * BS; i += 256) {
        int r = i >> 5, c = i & 31;
        sD[r * 33 + c]   = A[(size_t)(k * BS + r) * T + k * BS + c];
        sAkj[r * 33 + c] = A[(size_t)(k * BS + r) * T + jb * BS + c];
        sAik[r * 33 + c] = A[(size_t)(ib * BS + r) * T + k * BS + c];
    }
    __syncthreads();
    gj32(sD, tid);                       // sD = Di (ends with syncthreads)
    int ty = (tid >> 4) << 1, tx = (tid & 15) << 1;
    float b2[2][2] = {};
    mm32f(sD, sAkj, b2, ty, tx);         // B = Di * A[k][jb]  (== new row panel)
    sBB[(ty + 0) * 33 + tx + 0] = b2[0][0];
    sBB[(ty + 0) * 33 + tx + 1] = b2[0][1];
    sBB[(ty + 1) * 33 + tx + 0] = b2[1][0];
    sBB[(ty + 1) * 33 + tx + 1] = b2[1][1];
    __syncthreads();
    float acc[2][2] = {};
    mm32f(sAik, sBB, acc, ty, tx);
    for (int i = 0; i < 2; i++)
        for (int j = 0; j < 2; j++) {
            size_t idx = (size_t)(ib * BS + ty + i) * T + jb * BS + tx + j;
            A[idx] = A[idx] - acc[i][j];
        }
}

// ---------- sweep step kernel 2: row/col/diag panels ----------
// id<15: row jb ; 15<=id<30: col ib ; id==30: diag
__global__ void __launch_bounds__(256) k_sw_panel(int k) {
    int f = blockIdx.x, id = blockIdx.y;
    __shared__ float sD[BS * 33], sM[BS * 33];
    float* A = g_Kw + (size_t)f * T * T;
    int tid = threadIdx.x;
    int mode, ob = 0;
    if (id < 15) { mode = 0; ob = id + (id >= k ? 1 : 0); }
    else if (id < 30) { mode = 1; ob = (id - 15) + ((id - 15) >= k ? 1 : 0); }
    else mode = 2;
    for (int i = tid; i < BS * BS; i += 256) {
        int r = i >> 5, c = i & 31;
        sD[r * 33 + c] = A[(size_t)(k * BS + r) * T + k * BS + c];
        if (mode == 0) sM[r * 33 + c] = A[(size_t)(k * BS + r) * T + ob * BS + c];
        else if (mode == 1) sM[r * 33 + c] = A[(size_t)(ob * BS + r) * T + k * BS + c];
    }
    __syncthreads();
    gj32(sD, tid);
    if (mode == 2) {
        for (int i = tid; i < BS * BS; i += 256)
            A[(size_t)(k * BS + (i >> 5)) * T + k * BS + (i & 31)] = sD[(i >> 5) * 33 + (i & 31)];
        return;
    }
    int ty = (tid >> 4) << 1, tx = (tid & 15) << 1;
    float acc[2][2] = {};
    if (mode == 0) {
        mm32f(sD, sM, acc, ty, tx);      // Di * A[k][jb]
        for (int i = 0; i < 2; i++)
            for (int j = 0; j < 2; j++)
                A[(size_t)(k * BS + ty + i) * T + ob * BS + tx + j] = acc[i][j];
    } else {
        mm32f(sM, sD, acc, ty, tx);      // A[ib][k] * Di
        for (int i = 0; i < 2; i++)
            for (int j = 0; j < 2; j++)
                A[(size_t)(ob * BS + ty + i) * T + k * BS + tx + j] = -acc[i][j];
    }
}

// ---------- Newton GEMM (R14-proven verbatim, 64x64 tiles 4x4) ----------
__global__ void __launch_bounds__(256) k_gemm(int which) {
    int jb = blockIdx.x, ib = blockIdx.y, f = blockIdx.z;
    const float* A = (which ? g_Kw : g_K0) + (size_t)f * T * T;
    const float* Bm = (which ? g_Wn : g_Kw) + (size_t)f * T * T;
    float* C = (which ? g_K0 : g_Wn) + (size_t)f * T * T;
    __shared__ float sAT[GBS * SMS], sB[GBS * SMS];
    int tid = threadIdx.x;
    int ty4 = (tid >> 4) << 2, tx4 = (tid & 15) << 2;
    float acc[4][4] = {};
    for (int kc = 0; kc < T; kc += GBS) {
        __syncthreads();
        for (int i = tid; i < GBS * GBS / 4; i += 256) {
            int row = i >> 4, kg = (i & 15) << 2;
            float4 v = *(const float4*)(A + (size_t)(ib * GBS + row) * T + kc + kg);
            sAT[(kg + 0) * SMS + row] = v.x;
            sAT[(kg + 1) * SMS + row] = v.y;
            sAT[(kg + 2) * SMS + row] = v.z;
            sAT[(kg + 3) * SMS + row] = v.w;
        }
        for (int i = tid; i < GBS * GBS / 4; i += 256) {
            int kk = i >> 4, cg = (i & 15) << 2;
            *(float4*)(sB + kk * SMS + cg) =
                *(const float4*)(Bm + (size_t)(kc + kk) * T + jb * GBS + cg);
        }
        __syncthreads();
#pragma unroll
        for (int kk = 0; kk < GBS; kk++) {
            float4 a = *(const float4*)(sAT + kk * SMS + ty4);
            float4 b = *(const float4*)(sB + kk * SMS + tx4);
            acc[0][0] += a.x * b.x; acc[0][1] += a.x * b.y; acc[0][2] += a.x * b.z; acc[0][3] += a.x * b.w;
            acc[1][0] += a.y * b.x; acc[1][1] += a.y * b.y; acc[1][2] += a.y * b.z; acc[1][3] += a.y * b.w;
            acc[2][0] += a.z * b.x; acc[2][1] += a.z * b.y; acc[2][2] += a.z * b.z; acc[2][3] += a.z * b.w;
            acc[3][0] += a.w * b.x; acc[3][1] += a.w * b.y; acc[3][2] += a.w * b.z; acc[3][3] += a.w * b.w;
        }
    }
#pragma unroll
    for (int i = 0; i < 4; i++) {
        int row = ib * GBS + ty4 + i;
        int col0 = jb * GBS + tx4;
        float4 v;
        if (which) {
            v = make_float4(acc[i][0], acc[i][1], acc[i][2], acc[i][3]);
        } else {
            v.x = (row == col0 + 0 ? 2.f : 0.f) - acc[i][0];
            v.y = (row == col0 + 1 ? 2.f : 0.f) - acc[i][1];
            v.z = (row == col0 + 2 ? 2.f : 0.f) - acc[i][2];
            v.w = (row == col0 + 3 ? 2.f : 0.f) - acc[i][3];
        }
        *(float4*)(C + (size_t)row * T + col0) = v;
    }
}

// ---------- fused Ssum + Jacobi diag ----------
__global__ void k_sumd() {
    int i = blockIdx.x * 256 + threadIdx.x;
    if (i >= T * T) return;
    float s = 0.f;
#pragma unroll
    for (int f = 0; f < F; f++) s += g_K0[(size_t)f * T * T + i];
    g_Sf[i] = s;
    int t = i / T, u = i % T;
    if (t == u) {
#pragma unroll
        for (int f = 0; f < F; f++)
            g_invd[t * F + f] = 1.0f / (s + g_crc[f * F + f]);
    }
}

// ---------- term1 (proven verbatim) ----------
__global__ void __launch_bounds__(128) k_term1(const float* __restrict__ sp) {
    int r = blockIdx.x, tid = threadIdx.x;
    __shared__ float sc[F][NN];
    __shared__ float scd[F];
    for (int i = tid; i < F * NN; i += 128) sc[i / NN][i % NN] = g_crinv[i];
    if (tid < F) scd[tid] = g_cd[tid];
    __syncthreads();
    float ax[F], ay[F], az[F], aw[F];
#pragma unroll
    for (int f = 0; f < F; f++) { ax[f] = ay[f] = az[f] = aw[f] = 0.f; }
    const float4* S = (const float4*)(sp + (size_t)r * NN * T);
#pragma unroll 2
    for (int n = 0; n < NN; n++) {
        float4 v = S[n * (T / 4) + tid];
#pragma unroll
        for (int f = 0; f < F; f++) {
            float c = sc[f][n];
            ax[f] += c * v.x; ay[f] += c * v.y; az[f] += c * v.z; aw[f] += c * v.w;
        }
    }
    int t0 = tid * 4;
#pragma unroll
    for (int f = 0; f < F; f++) {
        g_B[((size_t)(t0 + 0) * F + f) * NR + r] = ax[f] - scd[f];
        g_B[((size_t)(t0 + 1) * F + f) * NR + r] = ay[f] - scd[f];
        g_B[((size_t)(t0 + 2) * F + f) * NR + r] = az[f] - scd[f];
        g_B[((size_t)(t0 + 3) * F + f) * NR + r] = aw[f] - scd[f];
    }
}

// ---------- CG init + rho0 (proven verbatim) ----------
__global__ void k_cginit() {
    int b = blockIdx.x, r = threadIdx.x;
    float part = 0.f;
    for (int i = 0; i < 64; i++) {
        int row = b * 64 + i;
        size_t idx = (size_t)row * NR + r;
        float bv = g_B[idx];
        float z = bv * g_invd[row];
        g_X[idx] = 0.f; g_Rv[idx] = bv; g_Z[idx] = z; g_P[idx] = z;
        part += z * bv;
    }
    g_zp0[b * NR + r] = part;
}

__global__ void k_rho0() {
    int r = threadIdx.x;
    float s = 0.f;
    for (int j = 0; j < 64; j++) s += g_zp0[j * NR + r];
    g_rho[0][r] = s;
}

// ---------- matvec (proven verbatim) ----------
__global__ void __launch_bounds__(256) k_matvec() {
    int fb = blockIdx.x, tb = blockIdx.y, t0 = tb * 32;
    __shared__ float sS[32][33];
    __shared__ float sP[32][128];
    __shared__ float scrc[F];
    __shared__ float sred[8][128];
    int tid = threadIdx.x;
    if (tid < F) scrc[tid] = g_crc[fb * F + tid];
    int ty = tid >> 5, tx = tid & 31;
    float4 acc[4];
#pragma unroll
    for (int i = 0; i < 4; i++) acc[i] = make_float4(0.f, 0.f, 0.f, 0.f);
    for (int uc = 0; uc < T; uc += 32) {
        __syncthreads();
        for (int i = tid; i < 32 * 32; i += 256)
            sS[i >> 5][i & 31] = g_Sf[(size_t)(t0 + (i >> 5)) * T + uc + (i & 31)];
        for (int i = tid; i < 32 * 32; i += 256)
            ((float4*)sP[i >> 5])[i & 31] =
                ((const float4*)(g_P + (size_t)(uc + (i >> 5)) * NW + fb * NR))[i & 31];
        __syncthreads();
#pragma unroll 8
        for (int uu = 0; uu < 32; uu++) {
            float4 pv = ((const float4*)sP[uu])[tx];
            float k0 = sS[ty * 4 + 0][uu], k1 = sS[ty * 4 + 1][uu];
            float k2 = sS[ty * 4 + 2][uu], k3 = sS[ty * 4 + 3][uu];
            acc[0].x += k0 * pv.x; acc[0].y += k0 * pv.y;
            acc[0].z += k0 * pv.z; acc[0].w += k0 * pv.w;
            acc[1].x += k1 * pv.x; acc[1].y += k1 * pv.y;
            acc[1].z += k1 * pv.z; acc[1].w += k1 * pv.w;
            acc[2].x += k2 * pv.x; acc[2].y += k2 * pv.y;
            acc[2].z += k2 * pv.z; acc[2].w += k2 * pv.w;
            acc[3].x += k3 * pv.x; acc[3].y += k3 * pv.y;
            acc[3].z += k3 * pv.z; acc[3].w += k3 * pv.w;
        }
    }
    float4 pf[4];
#pragma unroll
    for (int i = 0; i < 4; i++) pf[i] = make_float4(0.f, 0.f, 0.f, 0.f);
#pragma unroll
    for (int g = 0; g < F; g++) {
        float c = scrc[g];
#pragma unroll
        for (int i = 0; i < 4; i++) {
            float4 q = ((const float4*)(g_P + (size_t)(t0 + ty * 4 + i) * NW + g * NR))[tx];
            if (g == fb) pf[i] = q;
            acc[i].x += c * q.x; acc[i].y += c * q.y;
            acc[i].z += c * q.z; acc[i].w += c * q.w;
        }
    }
    float4 sd = make_float4(0.f, 0.f, 0.f, 0.f);
#pragma unroll
    for (int i = 0; i < 4; i++) {
        ((float4*)(g_AP + (size_t)(t0 + ty * 4 + i) * NW + fb * NR))[tx] = acc[i];
        sd.x += pf[i].x * acc[i].x; sd.y += pf[i].y * acc[i].y;
        sd.z += pf[i].z * acc[i].z; sd.w += pf[i].w * acc[i].w;
    }
    sred[ty][tx * 4 + 0] = sd.x; sred[ty][tx * 4 + 1] = sd.y;
    sred[ty][tx * 4 + 2] = sd.z; sred[ty][tx * 4 + 3] = sd.w;
    __syncthreads();
    if (tid < NR) {
        float s = 0.f;
#pragma unroll
        for (int w = 0; w < 8; w++) s += sred[w][tid];
        g_pAp[(fb * 16 + tb) * NR + tid] = s;
    }
}

__global__ void k_alpha(int par) {
    int r = threadIdx.x;
    float pap = 0.f;
    for (int j = 0; j < 128; j++) pap += g_pAp[j * NR + r];
    g_al[r] = g_rho[par][r] / pap;
}

__global__ void __launch_bounds__(256) k_upz() {
    int b = blockIdx.x, tid = threadIdx.x;
    __shared__ float4 sp4[256];
    float4 al = ((const float4*)g_al)[tid & 31];
    float4 part = make_float4(0.f, 0.f, 0.f, 0.f);
#pragma unroll
    for (int k = 0; k < 2; k++) {
        int f4 = b * 512 + k * 256 + tid;
        int row = f4 >> 5;
        float iv = g_invd[row];
        float4 p = ((const float4*)g_P)[f4];
        float4 ap = ((const float4*)g_AP)[f4];
        float4 x = ((const float4*)g_X)[f4];
        float4 rv = ((const float4*)g_Rv)[f4];
        x.x += al.x * p.x; x.y += al.y * p.y; x.z += al.z * p.z; x.w += al.w * p.w;
        rv.x -= al.x * ap.x; rv.y -= al.y * ap.y; rv.z -= al.z * ap.z; rv.w -= al.w * ap.w;
        float4 z = make_float4(iv * rv.x, iv * rv.y, iv * rv.z, iv * rv.w);
        ((float4*)g_X)[f4] = x;
        ((float4*)g_Rv)[f4] = rv;
        ((float4*)g_Z)[f4] = z;
        part.x += z.x * rv.x; part.y += z.y * rv.y;
        part.z += z.z * rv.z; part.w += z.w * rv.w;
    }
    sp4[tid] = part;
    __syncthreads();
    for (int off = 128; off >= 32; off >>= 1) {
        if (tid < off) {
            float4 o = sp4[tid + off];
            sp4[tid].x += o.x; sp4[tid].y += o.y; sp4[tid].z += o.z; sp4[tid].w += o.w;
        }
        __syncthreads();
    }
    if (tid < 32) g_zpp[b * 32 + tid] = sp4[tid];
}

__global__ void k_beta(int par) {
    int r = threadIdx.x;
    int rc = r >> 2, comp = r & 3;
    float s = 0.f;
    for (int b = 0; b < 256; b++) {
        float4 v = g_zpp[b * 32 + rc];
        s += comp == 0 ? v.x : comp == 1 ? v.y : comp == 2 ? v.z : v.w;
    }
    g_rho[par ^ 1][r] = s;
    g_be[r] = s / g_rho[par][r];
}

__global__ void __launch_bounds__(256) k_pup() {
    int f4 = blockIdx.x * 256 + threadIdx.x;
    float4 be = ((const float4*)g_be)[threadIdx.x & 31];
    float4 p = ((const float4*)g_P)[f4];
    float4 z = ((const float4*)g_Z)[f4];
    p.x = z.x + be.x * p.x; p.y = z.y + be.y * p.y;
    p.z = z.z + be.z * p.z; p.w = z.w + be.w * p.w;
    ((float4*)g_P)[f4] = p;
}

// ---------- out (proven verbatim) ----------
__global__ void k_out(float* __restrict__ out) {
    __shared__ float s[32][129];
    int base = blockIdx.x * 32, tid = threadIdx.x;
    for (int i = tid; i < 32 * NR; i += 256)
        s[i >> 7][i & 127] = g_X[(size_t)(base + (i >> 7)) * NR + (i & 127)];
    __syncthreads();
    for (int i = tid; i < 32 * NR; i += 256) {
        int r = i >> 5, row = i & 31, grow = base + row;
        int t = grow >> 3, f = grow & 7;
        out[(size_t)r * FT + f * T + t] = s[row][r];
    }
}

extern "C" void kernel_launch(void* const* d_in, const int* in_sizes, int n_in,
                              void* d_out, int out_size) {
    const float* sp = (const float*)d_in[0];
    const float* Cm = (const float*)d_in[1];
    const float* dm = (const float*)d_in[2];
    const float* rd = (const float*)d_in[3];
    const float* gm = (const float*)d_in[4];
    float* out = (float*)d_out;

    k_setup<<<1, 256>>>(Cm, dm, rd);
    k_buildK<<<dim3(T, F), 128>>>(gm);
    for (int k = 0; k < NB; k++) {
        k_sw_int<<<dim3(F, NB - 1, NB - 1), 256>>>(k);   // reads old panels
        k_sw_panel<<<dim3(F, 2 * (NB - 1) + 1), 256>>>(k); // writes row/col/diag
    }
    k_gemm<<<dim3(T / GBS, T / GBS, F), 256>>>(0);
    k_gemm<<<dim3(T / GBS, T / GBS, F), 256>>>(1);
    k_sumd<<<(T * T + 255) / 256, 256>>>();
    k_term1<<<NR, 128>>>(sp);
    k_cginit<<<64, 128>>>();
    k_rho0<<<1, 128>>>();
    for (int it = 0; it < NITER; it++) {
        int par = it & 1;
        k_matvec<<<dim3(F, 16), 256>>>();
        k_alpha<<<1, 128>>>(par);
        k_upz<<<256, 256>>>();
        if (it < NITER - 1) {
            k_beta<<<1, 128>>>(par);
            k_pup<<<512, 256>>>();
        }
    }
    k_out<<<FT / 32, 256>>>(out);
}

// round 17
// speedup vs baseline: 1.8930x; 1.8930x over previous
#include <cuda_runtime.h>

#define F 8
#define T 512
#define NN 512
#define NR 128
#define FT 4096
#define NW 1024
#define BS 32
#define NB 16
#define NITER 12
#define GBS 64
#define SMS 68

__device__ float g_K0[F * T * T];
__device__ float g_Kw[F * T * T];
__device__ float g_Wn[F * T * T];
__device__ float g_Sf[T * T];
__device__ float g_Di[F * BS * BS];
__device__ float g_crinv[F * NN], g_crc[F * F], g_cd[F], g_invd[FT];
__device__ float g_B[FT * NR], g_X[FT * NR], g_Rv[FT * NR];
__device__ float g_Z[FT * NR], g_P[FT * NR], g_AP[FT * NR];
__device__ float g_pAp[128 * NR];
__device__ float g_zp0[64 * NR];
__device__ float4 g_zpp[256 * 32];
__device__ float g_rho[2][NR], g_al[NR], g_be[NR];

// ---------- setup (proven verbatim) ----------
__global__ void k_setup(const float* __restrict__ Cm, const float* __restrict__ dm,
                        const float* __restrict__ rd) {
    int tid = threadIdx.x;
    for (int i = tid; i < F * NN; i += 256) {
        int f = i / NN, n = i % NN;
        g_crinv[f * NN + n] = Cm[n * F + f] / rd[n];
    }
    __syncthreads();
    int w = tid >> 5, l = tid & 31;
    for (int q = 0; q < 8; q++) {
        int e = w * 8 + q, i = e / F, j = e % F;
        float s = 0.f;
        for (int n = l; n < NN; n += 32) s += g_crinv[i * NN + n] * Cm[n * F + j];
        for (int o = 16; o; o >>= 1) s += __shfl_xor_sync(0xffffffffu, s, o);
        if (l == 0) g_crc[e] = s;
    }
    {
        float s = 0.f;
        for (int n = l; n < NN; n += 32) s += g_crinv[w * NN + n] * dm[n];
        for (int o = 16; o; o >>= 1) s += __shfl_xor_sync(0xffffffffu, s, o);
        if (l == 0) g_cd[w] = s;
    }
}

// ---------- build K (proven verbatim) ----------
__global__ void k_buildK(const float* __restrict__ gm) {
    int t = blockIdx.x, f = blockIdx.y;
    float g = gm[f];
    size_t base = ((size_t)f * T + t) * T;
    for (int u = threadIdx.x; u < T; u += blockDim.x) {
        float d = (float)(t - u);
        float v = (1.0f - 1e-3f) * expf(-0.5f * g * d * d);
        if (u == t) v += 1e-3f;
        g_K0[base + u] = v;
        g_Kw[base + u] = v;
    }
}

// ---------- GJ sweep (proven verbatim, BS=32) ----------
__global__ void k_diag(int k) {
    __shared__ float s[BS][BS + 1];
    int f = blockIdx.x, tid = threadIdx.x;
    float* A = g_Kw + (size_t)f * T * T;
    for (int i = tid; i < BS * BS; i += 256)
        s[i >> 5][i & 31] = A[(size_t)(k * BS + (i >> 5)) * T + k * BS + (i & 31)];
    __syncthreads();
    for (int p = 0; p < BS; p++) {
        float pv = 1.0f / s[p][p];
        for (int j = tid; j < BS; j += 256) if (j != p) s[p][j] *= pv;
        __syncthreads();
        for (int i = tid; i < BS * BS; i += 256) {
            int r = i >> 5, c = i & 31;
            if (r != p && c != p) s[r][c] -= s[r][p] * s[p][c];
        }
        __syncthreads();
        for (int i = tid; i < BS; i += 256) if (i != p) s[i][p] *= -pv;
        if (tid == 0) s[p][p] = pv;
        __syncthreads();
    }
    for (int i = tid; i < BS * BS; i += 256) g_Di[f * BS * BS + i] = s[i >> 5][i & 31];
}

__device__ __forceinline__ void mm32f(const float* sA, const float* sB,
                                      float acc[2][2], int ty, int tx) {
    for (int kk = 0; kk < BS; kk++) {
        float a0 = sA[(ty + 0) * 33 + kk], a1 = sA[(ty + 1) * 33 + kk];
        float b0 = sB[kk * 33 + tx + 0], b1 = sB[kk * 33 + tx + 1];
        acc[0][0] += a0 * b0; acc[0][1] += a0 * b1;
        acc[1][0] += a1 * b0; acc[1][1] += a1 * b1;
    }
}

__global__ void __launch_bounds__(256) k_row(int k) {
    int f = blockIdx.x, jb = blockIdx.y;
    if (jb == k) return;
    __shared__ float sD[BS * 33], sA[BS * 33];
    float* A = g_Kw + (size_t)f * T * T;
    int tid = threadIdx.x;
    for (int i = tid; i < BS * BS; i += 256) {
        sD[(i >> 5) * 33 + (i & 31)] = g_Di[f * BS * BS + i];
        sA[(i >> 5) * 33 + (i & 31)] = A[(size_t)(k * BS + (i >> 5)) * T + jb * BS + (i & 31)];
    }
    __syncthreads();
    int ty = (tid >> 4) << 1, tx = (tid & 15) << 1;
    float acc[2][2] = {};
    mm32f(sD, sA, acc, ty, tx);
    for (int i = 0; i < 2; i++)
        for (int j = 0; j < 2; j++)
            A[(size_t)(k * BS + ty + i) * T + jb * BS + tx + j] = acc[i][j];
}

// ---------- interior: two jb tiles per block, fused inner loop ----------
// A[ib][jb] -= A[ib][k]_old * A[k][jb]_new  for jb in {2*zb, 2*zb+1}, != k
__global__ void __launch_bounds__(256) k_int2(int k) {
    int f = blockIdx.x, ib = blockIdx.y;
    if (ib == k) return;
    int jb0 = blockIdx.z * 2, jb1 = jb0 + 1;
    bool do0 = (jb0 != k), do1 = (jb1 != k);
    __shared__ float sAik[BS * 33], sB0[BS * 33], sB1[BS * 33];
    float* A = g_Kw + (size_t)f * T * T;
    int tid = threadIdx.x;
    for (int i = tid; i < BS * BS; i += 256) {
        int r = i >> 5, c = i & 31;
        sAik[r * 33 + c] = A[(size_t)(ib * BS + r) * T + k * BS + c];
        if (do0) sB0[r * 33 + c] = A[(size_t)(k * BS + r) * T + jb0 * BS + c];
        if (do1) sB1[r * 33 + c] = A[(size_t)(k * BS + r) * T + jb1 * BS + c];
    }
    __syncthreads();
    int ty = (tid >> 4) << 1, tx = (tid & 15) << 1;
    float a0c[2][2] = {}, a1c[2][2] = {};
    for (int kk = 0; kk < BS; kk++) {
        float a0 = sAik[(ty + 0) * 33 + kk], a1 = sAik[(ty + 1) * 33 + kk];
        float b00 = sB0[kk * 33 + tx + 0], b01 = sB0[kk * 33 + tx + 1];
        float b10 = sB1[kk * 33 + tx + 0], b11 = sB1[kk * 33 + tx + 1];
        a0c[0][0] += a0 * b00; a0c[0][1] += a0 * b01;
        a0c[1][0] += a1 * b00; a0c[1][1] += a1 * b01;
        a1c[0][0] += a0 * b10; a1c[0][1] += a0 * b11;
        a1c[1][0] += a1 * b10; a1c[1][1] += a1 * b11;
    }
    if (do0)
        for (int i = 0; i < 2; i++)
            for (int j = 0; j < 2; j++) {
                size_t idx = (size_t)(ib * BS + ty + i) * T + jb0 * BS + tx + j;
                A[idx] = A[idx] - a0c[i][j];
            }
    if (do1)
        for (int i = 0; i < 2; i++)
            for (int j = 0; j < 2; j++) {
                size_t idx = (size_t)(ib * BS + ty + i) * T + jb1 * BS + tx + j;
                A[idx] = A[idx] - a1c[i][j];
            }
}

__global__ void __launch_bounds__(256) k_col(int k) {
    int f = blockIdx.x, ib = blockIdx.y;
    float* A = g_Kw + (size_t)f * T * T;
    int tid = threadIdx.x;
    if (ib == k) {
        for (int i = tid; i < BS * BS; i += 256)
            A[(size_t)(k * BS + (i >> 5)) * T + k * BS + (i & 31)] = g_Di[f * BS * BS + i];
        return;
    }
    __shared__ float sA[BS * 33], sD[BS * 33];
    for (int i = tid; i < BS * BS; i += 256) {
        sA[(i >> 5) * 33 + (i & 31)] = A[(size_t)(ib * BS + (i >> 5)) * T + k * BS + (i & 31)];
        sD[(i >> 5) * 33 + (i & 31)] = g_Di[f * BS * BS + i];
    }
    __syncthreads();
    int ty = (tid >> 4) << 1, tx = (tid & 15) << 1;
    float acc[2][2] = {};
    mm32f(sA, sD, acc, ty, tx);
    for (int i = 0; i < 2; i++)
        for (int j = 0; j < 2; j++)
            A[(size_t)(ib * BS + ty + i) * T + k * BS + tx + j] = -acc[i][j];
}

// ---------- Newton GEMM (R14-proven verbatim, 64x64 tiles 4x4) ----------
__global__ void __launch_bounds__(256) k_gemm(int which) {
    int jb = blockIdx.x, ib = blockIdx.y, f = blockIdx.z;
    const float* A = (which ? g_Kw : g_K0) + (size_t)f * T * T;
    const float* Bm = (which ? g_Wn : g_Kw) + (size_t)f * T * T;
    float* C = (which ? g_K0 : g_Wn) + (size_t)f * T * T;
    __shared__ float sAT[GBS * SMS], sB[GBS * SMS];
    int tid = threadIdx.x;
    int ty4 = (tid >> 4) << 2, tx4 = (tid & 15) << 2;
    float acc[4][4] = {};
    for (int kc = 0; kc < T; kc += GBS) {
        __syncthreads();
        for (int i = tid; i < GBS * GBS / 4; i += 256) {
            int row = i >> 4, kg = (i & 15) << 2;
            float4 v = *(const float4*)(A + (size_t)(ib * GBS + row) * T + kc + kg);
            sAT[(kg + 0) * SMS + row] = v.x;
            sAT[(kg + 1) * SMS + row] = v.y;
            sAT[(kg + 2) * SMS + row] = v.z;
            sAT[(kg + 3) * SMS + row] = v.w;
        }
        for (int i = tid; i < GBS * GBS / 4; i += 256) {
            int kk = i >> 4, cg = (i & 15) << 2;
            *(float4*)(sB + kk * SMS + cg) =
                *(const float4*)(Bm + (size_t)(kc + kk) * T + jb * GBS + cg);
        }
        __syncthreads();
#pragma unroll
        for (int kk = 0; kk < GBS; kk++) {
            float4 a = *(const float4*)(sAT + kk * SMS + ty4);
            float4 b = *(const float4*)(sB + kk * SMS + tx4);
            acc[0][0] += a.x * b.x; acc[0][1] += a.x * b.y; acc[0][2] += a.x * b.z; acc[0][3] += a.x * b.w;
            acc[1][0] += a.y * b.x; acc[1][1] += a.y * b.y; acc[1][2] += a.y * b.z; acc[1][3] += a.y * b.w;
            acc[2][0] += a.z * b.x; acc[2][1] += a.z * b.y; acc[2][2] += a.z * b.z; acc[2][3] += a.z * b.w;
            acc[3][0] += a.w * b.x; acc[3][1] += a.w * b.y; acc[3][2] += a.w * b.z; acc[3][3] += a.w * b.w;
        }
    }
#pragma unroll
    for (int i = 0; i < 4; i++) {
        int row = ib * GBS + ty4 + i;
        int col0 = jb * GBS + tx4;
        float4 v;
        if (which) {
            v = make_float4(acc[i][0], acc[i][1], acc[i][2], acc[i][3]);
        } else {
            v.x = (row == col0 + 0 ? 2.f : 0.f) - acc[i][0];
            v.y = (row == col0 + 1 ? 2.f : 0.f) - acc[i][1];
            v.z = (row == col0 + 2 ? 2.f : 0.f) - acc[i][2];
            v.w = (row == col0 + 3 ? 2.f : 0.f) - acc[i][3];
        }
        *(float4*)(C + (size_t)row * T + col0) = v;
    }
}

__global__ void k_sum() {
    int i = blockIdx.x * 256 + threadIdx.x;
    if (i >= T * T) return;
    float s = 0.f;
#pragma unroll
    for (int f = 0; f < F; f++) s += g_K0[(size_t)f * T * T + i];
    g_Sf[i] = s;
}

__global__ void k_invd() {
    int i = blockIdx.x * 256 + threadIdx.x;
    if (i >= FT) return;
    int t = i >> 3, f = i & 7;
    g_invd[i] = 1.0f / (g_Sf[(size_t)t * T + t] + g_crc[f * F + f]);
}

// ---------- term1 (proven verbatim) ----------
__global__ void __launch_bounds__(128) k_term1(const float* __restrict__ sp) {
    int r = blockIdx.x, tid = threadIdx.x;
    __shared__ float sc[F][NN];
    __shared__ float scd[F];
    for (int i = tid; i < F * NN; i += 128) sc[i / NN][i % NN] = g_crinv[i];
    if (tid < F) scd[tid] = g_cd[tid];
    __syncthreads();
    float ax[F], ay[F], az[F], aw[F];
#pragma unroll
    for (int f = 0; f < F; f++) { ax[f] = ay[f] = az[f] = aw[f] = 0.f; }
    const float4* S = (const float4*)(sp + (size_t)r * NN * T);
#pragma unroll 2
    for (int n = 0; n < NN; n++) {
        float4 v = S[n * (T / 4) + tid];
#pragma unroll
        for (int f = 0; f < F; f++) {
            float c = sc[f][n];
            ax[f] += c * v.x; ay[f] += c * v.y; az[f] += c * v.z; aw[f] += c * v.w;
        }
    }
    int t0 = tid * 4;
#pragma unroll
    for (int f = 0; f < F; f++) {
        g_B[((size_t)(t0 + 0) * F + f) * NR + r] = ax[f] - scd[f];
        g_B[((size_t)(t0 + 1) * F + f) * NR + r] = ay[f] - scd[f];
        g_B[((size_t)(t0 + 2) * F + f) * NR + r] = az[f] - scd[f];
        g_B[((size_t)(t0 + 3) * F + f) * NR + r] = aw[f] - scd[f];
    }
}

// ---------- CG init (proven verbatim) ----------
__global__ void k_cginit() {
    int b = blockIdx.x, r = threadIdx.x;
    float part = 0.f;
    for (int i = 0; i < 64; i++) {
        int row = b * 64 + i;
        size_t idx = (size_t)row * NR + r;
        float bv = g_B[idx];
        float z = bv * g_invd[row];
        g_X[idx] = 0.f; g_Rv[idx] = bv; g_Z[idx] = z; g_P[idx] = z;
        part += z * bv;
    }
    g_zp0[b * NR + r] = part;
}

// rho0: one block per r, tree reduce 64 partials
__global__ void k_rho0() {
    int r = blockIdx.x, tid = threadIdx.x;   // 128 x 64
    __shared__ float sr[64];
    sr[tid] = g_zp0[tid * NR + r];
    __syncthreads();
    for (int o = 32; o; o >>= 1) {
        if (tid < o) sr[tid] += sr[tid + o];
        __syncthreads();
    }
    if (tid == 0) g_rho[0][r] = sr[0];
}

// ---------- matvec (proven verbatim) ----------
__global__ void __launch_bounds__(256) k_matvec() {
    int fb = blockIdx.x, tb = blockIdx.y, t0 = tb * 32;
    __shared__ float sS[32][33];
    __shared__ float sP[32][128];
    __shared__ float scrc[F];
    __shared__ float sred[8][128];
    int tid = threadIdx.x;
    if (tid < F) scrc[tid] = g_crc[fb * F + tid];
    int ty = tid >> 5, tx = tid & 31;
    float4 acc[4];
#pragma unroll
    for (int i = 0; i < 4; i++) acc[i] = make_float4(0.f, 0.f, 0.f, 0.f);
    for (int uc = 0; uc < T; uc += 32) {
        __syncthreads();
        for (int i = tid; i < 32 * 32; i += 256)
            sS[i >> 5][i & 31] = g_Sf[(size_t)(t0 + (i >> 5)) * T + uc + (i & 31)];
        for (int i = tid; i < 32 * 32; i += 256)
            ((float4*)sP[i >> 5])[i & 31] =
                ((const float4*)(g_P + (size_t)(uc + (i >> 5)) * NW + fb * NR))[i & 31];
        __syncthreads();
#pragma unroll 8
        for (int uu = 0; uu < 32; uu++) {
            float4 pv = ((const float4*)sP[uu])[tx];
            float k0 = sS[ty * 4 + 0][uu], k1 = sS[ty * 4 + 1][uu];
            float k2 = sS[ty * 4 + 2][uu], k3 = sS[ty * 4 + 3][uu];
            acc[0].x += k0 * pv.x; acc[0].y += k0 * pv.y;
            acc[0].z += k0 * pv.z; acc[0].w += k0 * pv.w;
            acc[1].x += k1 * pv.x; acc[1].y += k1 * pv.y;
            acc[1].z += k1 * pv.z; acc[1].w += k1 * pv.w;
            acc[2].x += k2 * pv.x; acc[2].y += k2 * pv.y;
            acc[2].z += k2 * pv.z; acc[2].w += k2 * pv.w;
            acc[3].x += k3 * pv.x; acc[3].y += k3 * pv.y;
            acc[3].z += k3 * pv.z; acc[3].w += k3 * pv.w;
        }
    }
    float4 pf[4];
#pragma unroll
    for (int i = 0; i < 4; i++) pf[i] = make_float4(0.f, 0.f, 0.f, 0.f);
#pragma unroll
    for (int g = 0; g < F; g++) {
        float c = scrc[g];
#pragma unroll
        for (int i = 0; i < 4; i++) {
            float4 q = ((const float4*)(g_P + (size_t)(t0 + ty * 4 + i) * NW + g * NR))[tx];
            if (g == fb) pf[i] = q;
            acc[i].x += c * q.x; acc[i].y += c * q.y;
            acc[i].z += c * q.z; acc[i].w += c * q.w;
        }
    }
    float4 sd = make_float4(0.f, 0.f, 0.f, 0.f);
#pragma unroll
    for (int i = 0; i < 4; i++) {
        ((float4*)(g_AP + (size_t)(t0 + ty * 4 + i) * NW + fb * NR))[tx] = acc[i];
        sd.x += pf[i].x * acc[i].x; sd.y += pf[i].y * acc[i].y;
        sd.z += pf[i].z * acc[i].z; sd.w += pf[i].w * acc[i].w;
    }
    sred[ty][tx * 4 + 0] = sd.x; sred[ty][tx * 4 + 1] = sd.y;
    sred[ty][tx * 4 + 2] = sd.z; sred[ty][tx * 4 + 3] = sd.w;
    __syncthreads();
    if (tid < NR) {
        float s = 0.f;
#pragma unroll
        for (int w = 0; w < 8; w++) s += sred[w][tid];
        g_pAp[(fb * 16 + tb) * NR + tid] = s;
    }
}

// alpha: one block per r, tree reduce 128 partials
__global__ void k_alpha(int par) {
    int r = blockIdx.x, tid = threadIdx.x;   // 128 x 128
    __shared__ float sr[128];
    sr[tid] = g_pAp[tid * NR + r];
    __syncthreads();
    for (int o = 64; o; o >>= 1) {
        if (tid < o) sr[tid] += sr[tid + o];
        __syncthreads();
    }
    if (tid == 0) g_al[r] = g_rho[par][r] / sr[0];
}

__global__ void __launch_bounds__(256) k_upz() {
    int b = blockIdx.x, tid = threadIdx.x;
    __shared__ float4 sp4[256];
    float4 al = ((const float4*)g_al)[tid & 31];
    float4 part = make_float4(0.f, 0.f, 0.f, 0.f);
#pragma unroll
    for (int k = 0; k < 2; k++) {
        int f4 = b * 512 + k * 256 + tid;
        int row = f4 >> 5;
        float iv = g_invd[row];
        float4 p = ((const float4*)g_P)[f4];
        float4 ap = ((const float4*)g_AP)[f4];
        float4 x = ((const float4*)g_X)[f4];
        float4 rv = ((const float4*)g_Rv)[f4];
        x.x += al.x * p.x; x.y += al.y * p.y; x.z += al.z * p.z; x.w += al.w * p.w;
        rv.x -= al.x * ap.x; rv.y -= al.y * ap.y; rv.z -= al.z * ap.z; rv.w -= al.w * ap.w;
        float4 z = make_float4(iv * rv.x, iv * rv.y, iv * rv.z, iv * rv.w);
        ((float4*)g_X)[f4] = x;
        ((float4*)g_Rv)[f4] = rv;
        ((float4*)g_Z)[f4] = z;
        part.x += z.x * rv.x; part.y += z.y * rv.y;
        part.z += z.z * rv.z; part.w += z.w * rv.w;
    }
    sp4[tid] = part;
    __syncthreads();
    for (int off = 128; off >= 32; off >>= 1) {
        if (tid < off) {
            float4 o = sp4[tid + off];
            sp4[tid].x += o.x; sp4[tid].y += o.y; sp4[tid].z += o.z; sp4[tid].w += o.w;
        }
        __syncthreads();
    }
    if (tid < 32) g_zpp[b * 32 + tid] = sp4[tid];
}

// beta: one block per r, tree reduce 256 partials (2 loads/thread)
__global__ void k_beta(int par) {
    int r = blockIdx.x, tid = threadIdx.x;   // 128 x 128
    int rc = r >> 2, comp = r & 3;
    __shared__ float sr[128];
    float s = 0.f;
    for (int b = tid; b < 256; b += 128) {
        float4 v = g_zpp[b * 32 + rc];
        s += comp == 0 ? v.x : comp == 1 ? v.y : comp == 2 ? v.z : v.w;
    }
    sr[tid] = s;
    __syncthreads();
    for (int o = 64; o; o >>= 1) {
        if (tid < o) sr[tid] += sr[tid + o];
        __syncthreads();
    }
    if (tid == 0) {
        g_rho[par ^ 1][r] = sr[0];
        g_be[r] = sr[0] / g_rho[par][r];
    }
}

__global__ void __launch_bounds__(256) k_pup() {
    int f4 = blockIdx.x * 256 + threadIdx.x;
    float4 be = ((const float4*)g_be)[threadIdx.x & 31];
    float4 p = ((const float4*)g_P)[f4];
    float4 z = ((const float4*)g_Z)[f4];
    p.x = z.x + be.x * p.x; p.y = z.y + be.y * p.y;
    p.z = z.z + be.z * p.z; p.w = z.w + be.w * p.w;
    ((float4*)g_P)[f4] = p;
}

// ---------- out (proven verbatim) ----------
__global__ void k_out(float* __restrict__ out) {
    __shared__ float s[32][129];
    int base = blockIdx.x * 32, tid = threadIdx.x;
    for (int i = tid; i < 32 * NR; i += 256)
        s[i >> 7][i & 127] = g_X[(size_t)(base + (i >> 7)) * NR + (i & 127)];
    __syncthreads();
    for (int i = tid; i < 32 * NR; i += 256) {
        int r = i >> 5, row = i & 31, grow = base + row;
        int t = grow >> 3, f = grow & 7;
        out[(size_t)r * FT + f * T + t] = s[row][r];
    }
}

extern "C" void kernel_launch(void* const* d_in, const int* in_sizes, int n_in,
                              void* d_out, int out_size) {
    const float* sp = (const float*)d_in[0];
    const float* Cm = (const float*)d_in[1];
    const float* dm = (const float*)d_in[2];
    const float* rd = (const float*)d_in[3];
    const float* gm = (const float*)d_in[4];
    float* out = (float*)d_out;

    k_setup<<<1, 256>>>(Cm, dm, rd);
    k_buildK<<<dim3(T, F), 128>>>(gm);
    for (int k = 0; k < NB; k++) {
        k_diag<<<F, 256>>>(k);
        k_row<<<dim3(F, NB), 256>>>(k);
        k_int2<<<dim3(F, NB, NB / 2), 256>>>(k);
        k_col<<<dim3(F, NB), 256>>>(k);
    }
    k_gemm<<<dim3(T / GBS, T / GBS, F), 256>>>(0);
    k_gemm<<<dim3(T / GBS, T / GBS, F), 256>>>(1);
    k_sum<<<(T * T + 255) / 256, 256>>>();
    k_invd<<<FT / 256, 256>>>();
    k_term1<<<NR, 128>>>(sp);
    k_cginit<<<64, 128>>>();
    k_rho0<<<NR, 64>>>();
    for (int it = 0; it < NITER; it++) {
        int par = it & 1;
        k_matvec<<<dim3(F, 16), 256>>>();
        k_alpha<<<NR, 128>>>(par);
        k_upz<<<256, 256>>>();
        if (it < NITER - 1) {
            k_beta<<<NR, 128>>>(par);
            k_pup<<<512, 256>>>();
        }
    }
    k_out<<<FT / 32, 256>>>(out);
}